// round 3
// baseline (speedup 1.0000x reference)
#include <cuda_runtime.h>

// 5x5 box-filter mean, reflect padding, NCHW fp32, H=W=512.
// Shared-memory-free: each warp owns a 128-wide strip (32 lanes x float4)
// and streams down TH rows. Horizontal overlap via warp shuffles, vertical
// via a 5-deep register ring. Lanes 0/31 fetch the 2-float x-halo (reflect).

#define IMG 512
#define TH  32          // rows per warp strip
#define SW  128         // strip width (floats) = 32 lanes * 4

__device__ __forceinline__ int refl(int x) {
    return (x < 0) ? -x : ((x >= IMG) ? (2 * IMG - 2 - x) : x);
}

__device__ __forceinline__ float4 hsum_row(const float* __restrict__ row,
                                           int colx, int lane,
                                           int xl0, int xl1, int xr0, int xr1)
{
    const float4 c = *reinterpret_cast<const float4*>(row + colx);

    float pz = __shfl_up_sync(0xffffffffu, c.z, 1);   // col -2
    float pw = __shfl_up_sync(0xffffffffu, c.w, 1);   // col -1
    float nx = __shfl_down_sync(0xffffffffu, c.x, 1); // col +4
    float ny = __shfl_down_sync(0xffffffffu, c.y, 1); // col +5

    if (lane == 0)  { pz = row[xl0]; pw = row[xl1]; }
    if (lane == 31) { nx = row[xr0]; ny = row[xr1]; }

    const float s = c.x + c.y + c.z + c.w;
    float4 h;
    h.x = (s - c.w) + pz + pw;   // cols -2..2
    h.y = s + pw;                // cols -1..3
    h.z = s + nx;                // cols  0..4
    h.w = (s - c.x) + nx + ny;   // cols  1..5
    return h;
}

__global__ __launch_bounds__(256)
void box5_kernel(const float* __restrict__ in, float* __restrict__ out)
{
    const int lane = threadIdx.x & 31;
    const int wid  = threadIdx.x >> 5;                 // 0..7

    const int tile_x = blockIdx.x * SW;                // 0..384
    const int tile_y = (blockIdx.y * 8 + wid) * TH;    // 0..480
    const float* __restrict__ img  = in  + (size_t)blockIdx.z * (IMG * IMG);
    float* __restrict__       oimg = out + (size_t)blockIdx.z * (IMG * IMG);

    const int colx = tile_x + lane * 4;

    // x-halo source columns (constant down the strip)
    const int xl0 = refl(tile_x - 2);
    const int xl1 = refl(tile_x - 1);
    const int xr0 = refl(tile_x + SW);
    const int xr1 = refl(tile_x + SW + 1);

    float4 h[5];

    // Prologue: horizontal sums for rows tile_y-2 .. tile_y+1 -> h[0..3]
    #pragma unroll
    for (int k = 0; k < 4; k++) {
        const int gy = refl(tile_y - 2 + k);
        h[k] = hsum_row(img + gy * IMG, colx, lane, xl0, xl1, xr0, xr1);
    }

    const float inv25 = 1.0f / 25.0f;
    float* obase = oimg + tile_y * IMG + colx;

    #pragma unroll
    for (int r = 0; r < TH; r++) {
        const int gy = refl(tile_y + r + 2);
        h[(r + 4) % 5] = hsum_row(img + gy * IMG, colx, lane, xl0, xl1, xr0, xr1);

        const float4 a = h[0], b = h[1], c = h[2], d = h[3], e = h[4];
        float4 o;
        o.x = (a.x + b.x + c.x + d.x + e.x) * inv25;
        o.y = (a.y + b.y + c.y + d.y + e.y) * inv25;
        o.z = (a.z + b.z + c.z + d.z + e.z) * inv25;
        o.w = (a.w + b.w + c.w + d.w + e.w) * inv25;
        *reinterpret_cast<float4*>(obase + r * IMG) = o;
    }
}

extern "C" void kernel_launch(void* const* d_in, const int* in_sizes, int n_in,
                              void* d_out, int out_size)
{
    const float* in = (const float*)d_in[0];
    float* out = (float*)d_out;

    const int planes = in_sizes[0] / (IMG * IMG);   // 96

    dim3 grid(IMG / SW, (IMG / TH) / 8, planes);    // (4, 2, 96)
    dim3 block(256);
    box5_kernel<<<grid, block>>>(in, out);
}

// round 4
// speedup vs baseline: 1.4786x; 1.4786x over previous
#include <cuda_runtime.h>

// 5x5 box-filter mean, reflect padding, NCHW fp32, H=W=512.
// smem-free separable filter: each thread front-batches 8 LDG.128 (rows
// orow-2..orow+5 at its float4 column), resolves the +-2 column overlap with
// warp shuffles (lanes 0/31 fetch the 2-float x-halo via scalar LDG), then
// emits 4 output rows with direct vertical 5-sums.

#define IMG 512
#define TW  128   // tile width  (floats) = 32 lanes * 4
#define TH  32    // tile height (rows)   = 8 warps * 4

__device__ __forceinline__ int refl(int x) {
    return (x < 0) ? -x : ((x >= IMG) ? (2 * IMG - 2 - x) : x);
}

__global__ __launch_bounds__(256)
void box5_kernel(const float* __restrict__ in, float* __restrict__ out)
{
    const int lane = threadIdx.x;       // 0..31 -> float4 column
    const int wrp  = threadIdx.y;       // 0..7  -> 4-row group

    const int tile_x = blockIdx.x * TW;
    const int tile_y = blockIdx.y * TH;
    const float* __restrict__ img  = in  + (size_t)blockIdx.z * (IMG * IMG);
    float* __restrict__       oimg = out + (size_t)blockIdx.z * (IMG * IMG);

    const int colx  = tile_x + lane * 4;
    const int rbase = tile_y + wrp * 4 - 2;   // first of 8 input rows

    // ---- Front-batched loads: 8 rows x LDG.128 ----
    float4 c[8];
    int gy[8];
    #pragma unroll
    for (int k = 0; k < 8; k++) gy[k] = refl(rbase + k);
    #pragma unroll
    for (int k = 0; k < 8; k++)
        c[k] = *reinterpret_cast<const float4*>(img + gy[k] * IMG + colx);

    // ---- x-halo: lanes 0 and 31 fetch 2 reflected floats per row ----
    float e0[8], e1[8];
    if (lane == 0) {
        const int xl0 = refl(tile_x - 2), xl1 = refl(tile_x - 1);
        #pragma unroll
        for (int k = 0; k < 8; k++) {
            e0[k] = img[gy[k] * IMG + xl0];
            e1[k] = img[gy[k] * IMG + xl1];
        }
    } else if (lane == 31) {
        const int xr0 = refl(tile_x + TW), xr1 = refl(tile_x + TW + 1);
        #pragma unroll
        for (int k = 0; k < 8; k++) {
            e0[k] = img[gy[k] * IMG + xr0];
            e1[k] = img[gy[k] * IMG + xr1];
        }
    }

    // ---- Horizontal 5-sums via shuffles ----
    float4 h[8];
    #pragma unroll
    for (int k = 0; k < 8; k++) {
        float pz = __shfl_up_sync(0xffffffffu, c[k].z, 1);   // col -2
        float pw = __shfl_up_sync(0xffffffffu, c[k].w, 1);   // col -1
        float nx = __shfl_down_sync(0xffffffffu, c[k].x, 1); // col +4
        float ny = __shfl_down_sync(0xffffffffu, c[k].y, 1); // col +5
        if (lane == 0)  { pz = e0[k]; pw = e1[k]; }
        if (lane == 31) { nx = e0[k]; ny = e1[k]; }

        const float s = c[k].x + c[k].y + c[k].z + c[k].w;
        h[k].x = (s - c[k].w) + pz + pw;   // cols -2..2
        h[k].y = s + pw;                   // cols -1..3
        h[k].z = s + nx;                   // cols  0..4
        h[k].w = (s - c[k].x) + nx + ny;   // cols  1..5
    }

    // ---- Vertical 5-sums + scale + 4x STG.128 ----
    const float inv25 = 1.0f / 25.0f;
    float* obase = oimg + (tile_y + wrp * 4) * IMG + colx;

    #pragma unroll
    for (int r = 0; r < 4; r++) {
        float4 o;
        o.x = (h[r].x + h[r+1].x + h[r+2].x + h[r+3].x + h[r+4].x) * inv25;
        o.y = (h[r].y + h[r+1].y + h[r+2].y + h[r+3].y + h[r+4].y) * inv25;
        o.z = (h[r].z + h[r+1].z + h[r+2].z + h[r+3].z + h[r+4].z) * inv25;
        o.w = (h[r].w + h[r+1].w + h[r+2].w + h[r+3].w + h[r+4].w) * inv25;
        *reinterpret_cast<float4*>(obase + r * IMG) = o;
    }
}

extern "C" void kernel_launch(void* const* d_in, const int* in_sizes, int n_in,
                              void* d_out, int out_size)
{
    const float* in = (const float*)d_in[0];
    float* out = (float*)d_out;

    const int planes = in_sizes[0] / (IMG * IMG);   // 96

    dim3 grid(IMG / TW, IMG / TH, planes);          // (4, 16, 96)
    dim3 block(32, 8);
    box5_kernel<<<grid, block>>>(in, out);
}